// round 2
// baseline (speedup 1.0000x reference)
#include <cuda_runtime.h>
#include <math.h>

#define BATCH 8192
#define D1    129
#define KPAD  132           // K padded to multiple of 4 (zeros contribute nothing)
#define BM    128
#define BN    128
#define BK    44            // 132 = 3 * 44
#define NKC   3

// Scratch (allocation-free: __device__ globals)
__device__ float g_AT[KPAD * BATCH];   // [k][i] = z1[i][k]
__device__ float g_BT[KPAD * BATCH];   // [k][j] = metric[k] * z2[j][k]
__device__ float g_rowsum[BATCH];
__device__ float g_colsum[BATCH];
__device__ float g_diag[BATCH];        // sims[i][i]

__global__ void prep_kernel(const float* __restrict__ z1, const float* __restrict__ z2) {
    int idx = blockIdx.x * 256 + threadIdx.x;
    if (idx >= KPAD * BATCH) return;
    int k = idx / BATCH;
    int i = idx % BATCH;
    float a = 0.f, b = 0.f;
    if (k < D1) {
        a = z1[i * D1 + k];
        b = z2[i * D1 + k];
        if (k == 0) b = -b;          // Lorentz metric
    }
    g_AT[idx] = a;
    g_BT[idx] = b;
}

__global__ void zero_kernel() {
    int i = blockIdx.x * 256 + threadIdx.x;
    if (i < BATCH) { g_rowsum[i] = 0.f; g_colsum[i] = 0.f; }
}

__global__ __launch_bounds__(256) void gemm_fused_kernel() {
    __shared__ float As[BK][BM];   // K-major: As[k][row]
    __shared__ float Bs[BK][BN];   // K-major: Bs[k][col]

    const int tx = threadIdx.x & 15;      // 16 threads across cols
    const int ty = threadIdx.x >> 4;      // 16 threads across rows
    const int r0 = blockIdx.y * BM;
    const int c0 = blockIdx.x * BN;

    float acc[8][8];
    #pragma unroll
    for (int i = 0; i < 8; ++i)
        #pragma unroll
        for (int j = 0; j < 8; ++j) acc[i][j] = 0.f;

    for (int kc = 0; kc < NKC; ++kc) {
        const int kbase = kc * BK;
        // Load tiles: warp covers one k-row of 32 float4s -> fully coalesced, conflict-free
        for (int idx = threadIdx.x; idx < BK * (BM / 4); idx += 256) {
            int kk = idx >> 5;            // idx / 32
            int c4 = idx & 31;            // idx % 32
            *(float4*)&As[kk][c4 * 4] = *(const float4*)&g_AT[(kbase + kk) * BATCH + r0 + c4 * 4];
            *(float4*)&Bs[kk][c4 * 4] = *(const float4*)&g_BT[(kbase + kk) * BATCH + c0 + c4 * 4];
        }
        __syncthreads();

        #pragma unroll 4
        for (int kk = 0; kk < BK; ++kk) {
            float a[8], b[8];
            *(float4*)&a[0] = *(float4*)&As[kk][ty * 8];
            *(float4*)&a[4] = *(float4*)&As[kk][ty * 8 + 4];
            *(float4*)&b[0] = *(float4*)&Bs[kk][tx * 8];
            *(float4*)&b[4] = *(float4*)&Bs[kk][tx * 8 + 4];
            #pragma unroll
            for (int i = 0; i < 8; ++i)
                #pragma unroll
                for (int j = 0; j < 8; ++j)
                    acc[i][j] = fmaf(a[i], b[j], acc[i][j]);
        }
        __syncthreads();
    }

    // Epilogue: e = exp(-acosh(max(-inner, 1+eps)) / TEMP); accumulate row/col sums
    float rsum[8], csum[8];
    #pragma unroll
    for (int i = 0; i < 8; ++i) { rsum[i] = 0.f; csum[i] = 0.f; }

    const bool diag_block = (r0 == c0);
    #pragma unroll
    for (int i = 0; i < 8; ++i) {
        #pragma unroll
        for (int j = 0; j < 8; ++j) {
            float t = fmaxf(-acc[i][j], 1.0f + 1e-6f);
            float d = acoshf(t);
            float s = -d / 0.07f;
            float e = expf(s);
            rsum[i] += e;
            csum[j] += e;
            if (diag_block && (ty * 8 + i) == (tx * 8 + j))
                g_diag[r0 + ty * 8 + i] = s;
        }
    }

    // Row reduction: sum across tx (16-lane halves of each warp)
    #pragma unroll
    for (int i = 0; i < 8; ++i) {
        float v = rsum[i];
        v += __shfl_xor_sync(0xffffffffu, v, 1);
        v += __shfl_xor_sync(0xffffffffu, v, 2);
        v += __shfl_xor_sync(0xffffffffu, v, 4);
        v += __shfl_xor_sync(0xffffffffu, v, 8);
        if (tx == 0) atomicAdd(&g_rowsum[r0 + ty * 8 + i], v);
    }

    // Column reduction: stage per-thread partials in smem (reuse As), sum across ty
    __syncthreads();
    float* cs = &As[0][0];                // needs 16*128 floats; As holds 44*128
    #pragma unroll
    for (int j = 0; j < 8; ++j)
        cs[ty * BN + tx * 8 + j] = csum[j];
    __syncthreads();
    if (threadIdx.x < BN) {
        float v = 0.f;
        #pragma unroll
        for (int t = 0; t < 16; ++t) v += cs[t * BN + threadIdx.x];
        atomicAdd(&g_colsum[c0 + threadIdx.x], v);
    }
}

__global__ void final_kernel(float* __restrict__ out) {
    __shared__ float red[256];
    float s = 0.f;
    for (int i = threadIdx.x; i < BATCH; i += 256) {
        // loss_i = (LSE_row + LSE_col)/2 - sims_ii   (no max-shift needed: sims <= -0.02)
        s += 0.5f * (logf(g_rowsum[i]) + logf(g_colsum[i])) - g_diag[i];
    }
    red[threadIdx.x] = s;
    __syncthreads();
    for (int stride = 128; stride > 0; stride >>= 1) {
        if (threadIdx.x < stride) red[threadIdx.x] += red[threadIdx.x + stride];
        __syncthreads();
    }
    if (threadIdx.x == 0) out[0] = red[0] * (1.0f / (float)BATCH);
}

extern "C" void kernel_launch(void* const* d_in, const int* in_sizes, int n_in,
                              void* d_out, int out_size) {
    const float* z1 = (const float*)d_in[0];
    const float* z2 = (const float*)d_in[1];
    float* out = (float*)d_out;

    zero_kernel<<<(BATCH + 255) / 256, 256>>>();
    prep_kernel<<<(KPAD * BATCH + 255) / 256, 256>>>(z1, z2);
    dim3 grid(BATCH / BN, BATCH / BM);   // (cols, rows) = (64, 64)
    gemm_fused_kernel<<<grid, 256>>>();
    final_kernel<<<1, 256>>>(out);
}

// round 5
// speedup vs baseline: 4.7222x; 4.7222x over previous
#include <cuda_runtime.h>
#include <cuda_bf16.h>
#include <math.h>
#include <stdint.h>

#define BATCH 8192
#define D1    129
#define KDIM  128
#define TM    128
#define TN    128

#define TC_F  1.00000095367431640625f   // fp32(1 + 1e-6)
#define PEXP  (-14.285714285714285714f) // -1/0.07

// smem: A/B tiles with rows padded to 272B (17 x 16B groups -> conflict-free ldmatrix)
#define LDT_B   272u                     // bytes per row (128 bf16 = 256B + 16B pad)
#define SM_A    0u                       // 128 * 272 = 34816
#define SM_B    34816u                   // 128 * 272 = 34816
#define SM_A0   69632u                   // 128 floats
#define SM_B0   70144u                   // 128 floats
#define SMEM_BYTES 70656

// ---- device scratch (allocation-free) ----
__device__ __align__(256) __nv_bfloat16 g_A[BATCH * KDIM];
__device__ __align__(256) __nv_bfloat16 g_B[BATCH * KDIM];
__device__ float g_a0[BATCH], g_b0[BATCH];
__device__ float g_rowsum[BATCH], g_colsum[BATCH];
__device__ float g_loss;

__device__ __forceinline__ uint32_t smem_u32(const void* p) {
    uint32_t a;
    asm("{ .reg .u64 t; cvta.to.shared.u64 t, %1; cvt.u32.u64 %0, t; }" : "=r"(a) : "l"(p));
    return a;
}
__device__ __forceinline__ float f_sqrt(float x) { float r; asm("sqrt.approx.f32 %0, %1;" : "=f"(r) : "f"(x)); return r; }
__device__ __forceinline__ float f_lg2(float x)  { float r; asm("lg2.approx.f32 %0, %1;"  : "=f"(r) : "f"(x)); return r; }
__device__ __forceinline__ float f_ex2(float x)  { float r; asm("ex2.approx.f32 %0, %1;"  : "=f"(r) : "f"(x)); return r; }

__device__ __forceinline__ void ldsm_x4(uint32_t& r0, uint32_t& r1, uint32_t& r2, uint32_t& r3, uint32_t addr) {
    asm volatile("ldmatrix.sync.aligned.m8n8.x4.shared.b16 {%0,%1,%2,%3}, [%4];"
                 : "=r"(r0), "=r"(r1), "=r"(r2), "=r"(r3) : "r"(addr));
}
__device__ __forceinline__ void mma16816(float* c, const uint32_t* a, const uint32_t* b) {
    asm volatile("mma.sync.aligned.m16n8k16.row.col.f32.bf16.bf16.f32 "
                 "{%0,%1,%2,%3}, {%4,%5,%6,%7}, {%8,%9}, {%0,%1,%2,%3};"
                 : "+f"(c[0]), "+f"(c[1]), "+f"(c[2]), "+f"(c[3])
                 : "r"(a[0]), "r"(a[1]), "r"(a[2]), "r"(a[3]), "r"(b[0]), "r"(b[1]));
}

// ---- prep: bf16 operands (k=1..128), k=0 coords, zero accumulators ----
__global__ void prep_kernel(const float* __restrict__ z1, const float* __restrict__ z2) {
    int idx = blockIdx.x * 256 + threadIdx.x;
    if (idx < BATCH * KDIM) {
        int i = idx >> 7, kk = idx & 127;
        g_A[idx] = __float2bfloat16(z1[(size_t)i * D1 + 1 + kk]);
        g_B[idx] = __float2bfloat16(z2[(size_t)i * D1 + 1 + kk]);
    }
    if (idx < BATCH) {
        g_a0[idx] = z1[(size_t)idx * D1];
        g_b0[idx] = z2[(size_t)idx * D1];
        g_rowsum[idx] = 0.f;
        g_colsum[idx] = 0.f;
    }
    if (idx == 0) g_loss = 0.f;
}

// ---- fused HMMA GEMM + transcendental epilogue ----
__global__ __launch_bounds__(256, 2) void hyper_gemm_kernel() {
    extern __shared__ __align__(16) char sm[];
    const uint32_t sbase = smem_u32(sm);
    const int tid  = threadIdx.x;
    const int wid  = tid >> 5;
    const int lane = tid & 31;
    const int r0 = blockIdx.y * TM;
    const int c0 = blockIdx.x * TN;

    // Stage tiles: A rows = z1[r0..r0+127][k], B rows = z2[c0..c0+127][k], padded stride
    #pragma unroll
    for (int it = 0; it < 8; ++it) {
        int idx = tid + it * 256;                  // 0..2047
        int row = idx >> 4, ch = idx & 15;         // 16B chunk index
        uint32_t o = (uint32_t)row * LDT_B + (uint32_t)ch * 16u;
        *(uint4*)(sm + SM_A + o) = *(const uint4*)(g_A + (size_t)(r0 + row) * KDIM + ch * 8);
        *(uint4*)(sm + SM_B + o) = *(const uint4*)(g_B + (size_t)(c0 + row) * KDIM + ch * 8);
    }
    if (tid < TM) ((float*)(sm + SM_A0))[tid] = g_a0[r0 + tid];
    else if (tid < TM + TN) ((float*)(sm + SM_B0))[tid - TM] = g_b0[c0 + tid - TM];
    __syncthreads();

    // Warp tiling: 4 warp-rows x 2 warp-cols; warp tile = 32 (m) x 64 (n)
    const int mw = (wid & 3) * 32;
    const int nw = (wid >> 2) * 64;

    float acc[2][8][4];
    #pragma unroll
    for (int mi = 0; mi < 2; ++mi)
        #pragma unroll
        for (int ni = 0; ni < 8; ++ni)
            #pragma unroll
            for (int q = 0; q < 4; ++q) acc[mi][ni][q] = 0.f;

    const int lane8 = lane & 7, lm = lane >> 3;    // ldmatrix: matrix id + row-in-matrix
    // A x4: matrices {m0..7|k0, m8..15|k0, m0..7|k8, m8..15|k8}
    const uint32_t aAddrBase = sbase + SM_A
        + (uint32_t)(mw + ((lm & 1) << 3) + lane8) * LDT_B + (uint32_t)((lm >> 1) << 4);
    // B x4: matrices {n0..7|k0, n0..7|k8, n8..15|k0, n8..15|k8}
    const uint32_t bAddrBase = sbase + SM_B
        + (uint32_t)(nw + ((lm >> 1) << 3) + lane8) * LDT_B + (uint32_t)((lm & 1) << 4);

    #pragma unroll
    for (int ks = 0; ks < 8; ++ks) {
        uint32_t a[2][4], b[8][2];
        ldsm_x4(a[0][0], a[0][1], a[0][2], a[0][3], aAddrBase + ks * 32u);
        ldsm_x4(a[1][0], a[1][1], a[1][2], a[1][3], aAddrBase + ks * 32u + 16u * LDT_B);
        #pragma unroll
        for (int p = 0; p < 4; ++p)   // each x4 fills two 8-col n-fragments
            ldsm_x4(b[2 * p][0], b[2 * p][1], b[2 * p + 1][0], b[2 * p + 1][1],
                    bAddrBase + ks * 32u + (uint32_t)p * 16u * LDT_B);
        #pragma unroll
        for (int mi = 0; mi < 2; ++mi)
            #pragma unroll
            for (int ni = 0; ni < 8; ++ni)
                mma16816(acc[mi][ni], a[mi], b[ni]);
    }

    // ---- fused epilogue ----
    // acc[mi][ni][{c0,c1,c2,c3}]: rowA = mw + mi*16 + lane/4 (c0,c1), rowB = rowA+8 (c2,c3)
    //                              col  = nw + ni*8 + 2*(lane%4) (+1 for c1,c3)
    const float* sa0 = (const float*)(sm + SM_A0);
    const float* sb0 = (const float*)(sm + SM_B0);
    const int l4 = lane >> 2, l2 = lane & 3;

    float csum[16];
    #pragma unroll
    for (int q = 0; q < 16; ++q) csum[q] = 0.f;

    float rs[4];  // rowA(mi=0), rowB(mi=0), rowA(mi=1), rowB(mi=1)
    #pragma unroll
    for (int q = 0; q < 4; ++q) rs[q] = 0.f;

    #pragma unroll
    for (int mi = 0; mi < 2; ++mi) {
        const float a0A = sa0[mw + mi * 16 + l4];
        const float a0B = sa0[mw + mi * 16 + l4 + 8];
        #pragma unroll
        for (int ni = 0; ni < 8; ++ni) {
            const int colL = nw + ni * 8 + 2 * l2;
            const float b0L = sb0[colL], b0R = sb0[colL + 1];
            #pragma unroll
            for (int q = 0; q < 4; ++q) {
                const float aa = (q < 2) ? a0A : a0B;
                const float bb = (q & 1) ? b0R : b0L;
                float t = fmaf(aa, bb, -acc[mi][ni][q]);      // -inner
                t = fmaxf(t, TC_F);
                float u = t + f_sqrt((t - 1.0f) * (t + 1.0f));
                float e = f_ex2(PEXP * f_lg2(u));             // exp(-acosh(t)/0.07)
                rs[mi * 2 + (q >> 1)] += e;
                csum[ni * 2 + (q & 1)] += e;
            }
        }
    }

    // Row sums: reduce across the 4 lanes sharing l4 (xor 1,2), lane%4==0 commits
    #pragma unroll
    for (int q = 0; q < 4; ++q) {
        float v = rs[q];
        v += __shfl_xor_sync(0xffffffffu, v, 1);
        v += __shfl_xor_sync(0xffffffffu, v, 2);
        if (l2 == 0)
            atomicAdd(&g_rowsum[r0 + mw + (q >> 1) * 16 + (q & 1) * 8 + l4], v);
    }
    // Col sums: reduce across l4 groups (xor 4,8,16), lanes 0..3 commit
    #pragma unroll
    for (int q = 0; q < 16; ++q) {
        float v = csum[q];
        v += __shfl_xor_sync(0xffffffffu, v, 4);
        v += __shfl_xor_sync(0xffffffffu, v, 8);
        v += __shfl_xor_sync(0xffffffffu, v, 16);
        if (l4 == 0)
            atomicAdd(&g_colsum[c0 + nw + (q >> 1) * 8 + 2 * l2 + (q & 1)], v);
    }
}

// ---- loss: diag (recomputed from the same bf16 staging) + log-sums ----
__global__ void loss_kernel() {
    __shared__ float red[256];
    const int i = blockIdx.x * 256 + threadIdx.x;

    float dot = 0.f;
    const __nv_bfloat16* pa = g_A + (size_t)i * KDIM;
    const __nv_bfloat16* pb = g_B + (size_t)i * KDIM;
    #pragma unroll 8
    for (int k = 0; k < KDIM; ++k)
        dot = fmaf(__bfloat162float(pa[k]), __bfloat162float(pb[k]), dot);
    float t = fmaxf(fmaf(g_a0[i], g_b0[i], -dot), TC_F);
    float s_ii = -acoshf(t) * (1.0f / 0.07f);

    float part = 0.5f * (logf(g_rowsum[i]) + logf(g_colsum[i])) - s_ii;
    red[threadIdx.x] = part;
    __syncthreads();
    for (int s = 128; s > 0; s >>= 1) {
        if (threadIdx.x < s) red[threadIdx.x] += red[threadIdx.x + s];
        __syncthreads();
    }
    if (threadIdx.x == 0) atomicAdd(&g_loss, red[0]);
}

__global__ void write_kernel(float* __restrict__ out) {
    out[0] = g_loss * (1.0f / (float)BATCH);
}

extern "C" void kernel_launch(void* const* d_in, const int* in_sizes, int n_in,
                              void* d_out, int out_size) {
    const float* z1 = (const float*)d_in[0];
    const float* z2 = (const float*)d_in[1];
    float* out = (float*)d_out;

    static int configured = 0;
    if (!configured) {
        cudaFuncSetAttribute(hyper_gemm_kernel, cudaFuncAttributeMaxDynamicSharedMemorySize, SMEM_BYTES);
        configured = 1;
    }

    prep_kernel<<<(BATCH * KDIM + 255) / 256, 256>>>(z1, z2);
    dim3 grid(BATCH / TN, BATCH / TM);
    hyper_gemm_kernel<<<grid, 256, SMEM_BYTES>>>();
    loss_kernel<<<BATCH / 256, 256>>>();
    write_kernel<<<1, 1>>>(out);
}